// round 6
// baseline (speedup 1.0000x reference)
#include <cuda_runtime.h>
#include <cuda_bf16.h>
#include <cstdint>

namespace {
constexpr int B  = 8;
constexpr int S  = 1024;
constexpr int H  = 1024;
constexpr int NH = 16;
constexpr int HD = 64;
constexpr int M  = B * S;    // 8192
constexpr int BH = B * NH;   // 128
constexpr float SCALE  = 0.125f;
constexpr float LN_EPS = 1e-12f;
constexpr int BK = 32;

// GEMM smem (u16 units): 2 stages x (Ahi,Alo,Bhi,Blo each 128x40)
constexpr int GARR = 128 * 40;        // 5120
constexpr int GSTG = 4 * GARR;        // 20480
constexpr int GEMM_SMEM = 2 * GSTG * 2;  // 81920 bytes

// Flash smem (u16 units): Q hi/lo + 2 stages x (Khi,Klo,Vhi,Vlo each 128x72)
constexpr int FROW = 72;
constexpr int FQHI = 0;
constexpr int FQLO = 128 * FROW;              // 9216
constexpr int FKV0 = 2 * 128 * FROW;          // 18432
constexpr int FKVSTG = 4 * 128 * FROW;        // 36864
constexpr int FMASK_B = (FKV0 + 2 * FKVSTG) * 2;   // 184320 bytes
constexpr int FLASH_SMEM = FMASK_B + 2 * 128 * 4 + 256;  // 185600
}

// ---------------------------------------------------------------------------
// Scratch (allocation-free: __device__ globals)
// ---------------------------------------------------------------------------
__device__ __nv_bfloat16 g_hh[M * H],  g_hl[M * H];
__device__ __nv_bfloat16 g_wh[4u * H * H], g_wl[4u * H * H];
__device__ __nv_bfloat16 g_qh[BH*S*HD], g_ql[BH*S*HD];
__device__ __nv_bfloat16 g_kh[BH*S*HD], g_kl[BH*S*HD];
__device__ __nv_bfloat16 g_vh[BH*S*HD], g_vl[BH*S*HD];
__device__ __nv_bfloat16 g_ch[M * H],  g_cl[M * H];
__device__ float g_proj[M * H];

// ---------------------------------------------------------------------------
// helpers
// ---------------------------------------------------------------------------
__device__ __forceinline__ uint32_t smem_u32(const void* p) {
    uint32_t a;
    asm("{ .reg .u64 t; cvta.to.shared.u64 t, %1; cvt.u32.u64 %0, t; }"
        : "=r"(a) : "l"(p));
    return a;
}
__device__ __forceinline__ void mma_bf16(float* c, const uint32_t* a, const uint32_t* b) {
    asm volatile(
        "mma.sync.aligned.m16n8k16.row.col.f32.bf16.bf16.f32 "
        "{%0,%1,%2,%3}, {%4,%5,%6,%7}, {%8,%9}, {%0,%1,%2,%3};"
        : "+f"(c[0]), "+f"(c[1]), "+f"(c[2]), "+f"(c[3])
        : "r"(a[0]), "r"(a[1]), "r"(a[2]), "r"(a[3]), "r"(b[0]), "r"(b[1]));
}
__device__ __forceinline__ void ldm_x4(uint32_t* r, uint32_t addr) {
    asm volatile("ldmatrix.sync.aligned.m8n8.x4.shared.b16 {%0,%1,%2,%3}, [%4];"
                 : "=r"(r[0]), "=r"(r[1]), "=r"(r[2]), "=r"(r[3]) : "r"(addr));
}
__device__ __forceinline__ void ldm_x4t(uint32_t* r, uint32_t addr) {
    asm volatile("ldmatrix.sync.aligned.m8n8.x4.trans.shared.b16 {%0,%1,%2,%3}, [%4];"
                 : "=r"(r[0]), "=r"(r[1]), "=r"(r[2]), "=r"(r[3]) : "r"(addr));
}
__device__ __forceinline__ void split2(float x, float y, uint32_t& hi, uint32_t& lo) {
    asm("cvt.rn.bf16x2.f32 %0, %1, %2;" : "=r"(hi) : "f"(y), "f"(x));
    float hx = __uint_as_float(hi << 16);
    float hy = __uint_as_float(hi & 0xFFFF0000u);
    float rx = x - hx;
    float ry = y - hy;
    asm("cvt.rn.bf16x2.f32 %0, %1, %2;" : "=r"(lo) : "f"(ry), "f"(rx));
}
__device__ __forceinline__ void cpa16(uint32_t s, const void* g) {
    asm volatile("cp.async.cg.shared.global [%0], [%1], 16;" :: "r"(s), "l"(g));
}
__device__ __forceinline__ void cpa4(uint32_t s, const void* g) {
    asm volatile("cp.async.ca.shared.global [%0], [%1], 4;" :: "r"(s), "l"(g));
}
#define CP_COMMIT() asm volatile("cp.async.commit_group;" ::: "memory")
#define CP_WAIT0()  asm volatile("cp.async.wait_group 0;" ::: "memory")

// ---------------------------------------------------------------------------
// One-time fp32 -> hi/lo bf16 split.
// ---------------------------------------------------------------------------
__global__ __launch_bounds__(256, 8)
void cvt_split(const float* __restrict__ src, int sel)
{
    __nv_bfloat16* hi = (sel == 0) ? g_hh : g_wh + (size_t)(sel - 1) * H * H;
    __nv_bfloat16* lo = (sel == 0) ? g_hl : g_wl + (size_t)(sel - 1) * H * H;
    const size_t i = ((size_t)blockIdx.x * 256 + threadIdx.x) * 4;
    float4 f = *(const float4*)&src[i];
    uint32_t h0, l0, h1, l1;
    split2(f.x, f.y, h0, l0);
    split2(f.z, f.w, h1, l1);
    *(uint2*)&hi[i] = make_uint2(h0, h1);
    *(uint2*)&lo[i] = make_uint2(l0, l1);
}

// ---------------------------------------------------------------------------
// bf16 GEMM, cp.async 2-stage pipeline. C = X @ W^T + bias.
// 128x128 tile, 8 warps. dst_sel 0/1/2 -> q/k/v hi/lo; 3 -> g_proj fp32.
// ---------------------------------------------------------------------------
__global__ __launch_bounds__(256, 1)
void gemm_bf16(const float* __restrict__ bias, int dst_sel)
{
    extern __shared__ __align__(16) char gsm[];
    uint16_t* smu = (uint16_t*)gsm;

    const bool headsplit = dst_sel < 3;
    const __nv_bfloat16* Xhi = headsplit ? g_hh : g_ch;
    const __nv_bfloat16* Xlo = headsplit ? g_hl : g_cl;
    const __nv_bfloat16* Whi = g_wh + (size_t)dst_sel * H * H;
    const __nv_bfloat16* Wlo = g_wl + (size_t)dst_sel * H * H;
    __nv_bfloat16* dhi = (dst_sel == 0) ? g_qh : (dst_sel == 1) ? g_kh : g_vh;
    __nv_bfloat16* dlo = (dst_sel == 0) ? g_ql : (dst_sel == 1) ? g_kl : g_vl;

    const int tid  = threadIdx.x;
    const int lane = tid & 31;
    const int wid  = tid >> 5;
    const int bm   = blockIdx.y * 128;
    const int bn   = blockIdx.x * 128;
    const int m_off = (wid & 1) * 64;
    const int n_off = (wid >> 1) * 32;

    const int lr = tid >> 1;          // 0..127
    const int lk = (tid & 1) * 16;    // halves
    const __nv_bfloat16* xh = Xhi + (size_t)(bm + lr) * H + lk;
    const __nv_bfloat16* xl = Xlo + (size_t)(bm + lr) * H + lk;
    const __nv_bfloat16* wh = Whi + (size_t)(bn + lr) * H + lk;
    const __nv_bfloat16* wl = Wlo + (size_t)(bn + lr) * H + lk;

    // smem byte bases for this thread's copy slot, per stage
    const uint32_t smb = smem_u32(gsm);
    uint32_t dAh[2], dAl[2], dBh[2], dBl[2];
#pragma unroll
    for (int st = 0; st < 2; st++) {
        const uint32_t sb = smb + (uint32_t)(st * GSTG + lr * 40 + lk) * 2;
        dAh[st] = sb;
        dAl[st] = sb + GARR * 2;
        dBh[st] = sb + 2 * GARR * 2;
        dBl[st] = sb + 3 * GARR * 2;
    }

    auto prefetch = [&](int s, int st) {
        const int go = s * BK;   // halves
        cpa16(dAh[st],      xh + go);
        cpa16(dAh[st] + 16, xh + go + 8);
        cpa16(dAl[st],      xl + go);
        cpa16(dAl[st] + 16, xl + go + 8);
        cpa16(dBh[st],      wh + go);
        cpa16(dBh[st] + 16, wh + go + 8);
        cpa16(dBl[st],      wl + go);
        cpa16(dBl[st] + 16, wl + go + 8);
    };

    float acc[4][4][4];
#pragma unroll
    for (int i = 0; i < 4; i++)
#pragma unroll
        for (int j = 0; j < 4; j++)
#pragma unroll
            for (int t = 0; t < 4; t++) acc[i][j][t] = 0.f;

    prefetch(0, 0);
    CP_COMMIT();

    const int NS = H / BK;  // 32
    for (int s = 0; s < NS; s++) {
        const int st = s & 1;
        CP_WAIT0();
        __syncthreads();
        if (s + 1 < NS) { prefetch(s + 1, st ^ 1); CP_COMMIT(); }

        const uint16_t* Ahi = smu + st * GSTG;
        const uint16_t* Alo = Ahi + GARR;
        const uint16_t* Bhi = Ahi + 2 * GARR;
        const uint16_t* Blo = Ahi + 3 * GARR;

#pragma unroll
        for (int kk = 0; kk < 2; kk++) {
            const int kel = kk * 16;
            uint32_t ah[4][4], al[4][4], bh[2][4], bl[2][4];
            const int ar = m_off + (lane & 15);
            const int ac = kel + (lane >> 4) * 8;
#pragma unroll
            for (int mi = 0; mi < 4; mi++) {
                ldm_x4(ah[mi], smem_u32(&Ahi[(ar + mi * 16) * 40 + ac]));
                ldm_x4(al[mi], smem_u32(&Alo[(ar + mi * 16) * 40 + ac]));
            }
            const int br = n_off + (lane & 7) + ((lane >> 4) & 1) * 8;
            const int bc = kel + ((lane >> 3) & 1) * 8;
#pragma unroll
            for (int np = 0; np < 2; np++) {
                ldm_x4(bh[np], smem_u32(&Bhi[(br + np * 16) * 40 + bc]));
                ldm_x4(bl[np], smem_u32(&Blo[(br + np * 16) * 40 + bc]));
            }
#pragma unroll
            for (int mi = 0; mi < 4; mi++)
#pragma unroll
                for (int np = 0; np < 2; np++)
#pragma unroll
                    for (int half = 0; half < 2; half++) {
                        const int ni = np * 2 + half;
                        const uint32_t* bhp = &bh[np][half * 2];
                        const uint32_t* blp = &bl[np][half * 2];
                        mma_bf16(acc[mi][ni], ah[mi], bhp);
                        mma_bf16(acc[mi][ni], ah[mi], blp);
                        mma_bf16(acc[mi][ni], al[mi], bhp);
                    }
        }
        __syncthreads();
    }

#pragma unroll
    for (int mi = 0; mi < 4; mi++) {
#pragma unroll
        for (int ni = 0; ni < 4; ni++) {
            const int col = bn + n_off + ni * 8 + (lane & 3) * 2;
            const float2 bs = *(const float2*)&bias[col];
#pragma unroll
            for (int h2 = 0; h2 < 2; h2++) {
                const int row = bm + m_off + mi * 16 + (lane >> 2) + h2 * 8;
                float vx = acc[mi][ni][h2 * 2 + 0] + bs.x;
                float vy = acc[mi][ni][h2 * 2 + 1] + bs.y;
                if (headsplit) {
                    const int b_ = row >> 10, s_ = row & 1023;
                    const int h_ = col >> 6,  d_ = col & 63;
                    const size_t idx = ((size_t)(b_ * NH + h_) * S + s_) * HD + d_;
                    uint32_t hp, lp;
                    split2(vx, vy, hp, lp);
                    *(uint32_t*)&dhi[idx] = hp;
                    *(uint32_t*)&dlo[idx] = lp;
                } else {
                    float2 v; v.x = vx; v.y = vy;
                    *(float2*)&g_proj[(size_t)row * H + col] = v;
                }
            }
        }
    }
}

// ---------------------------------------------------------------------------
// Flash attention, cp.async 2-stage K/V pipeline. Block = (q-tile, head).
// ---------------------------------------------------------------------------
__global__ __launch_bounds__(256, 1)
void flash_attn(const float* __restrict__ mask)
{
    extern __shared__ __align__(16) char fsm[];
    uint16_t* smu = (uint16_t*)fsm;
    uint16_t* sQhi = smu + FQHI;
    uint16_t* sQlo = smu + FQLO;

    const int head = blockIdx.y;
    const int b_   = head >> 4;
    const int h_   = head & 15;
    const size_t hbase = (size_t)head * S * HD;
    const float* mrow = mask + (size_t)b_ * S;

    const int tid  = threadIdx.x;
    const int lane = tid & 31;
    const int w    = tid >> 5;
    const int bq   = blockIdx.x * 128;

    const int lr = tid >> 1;          // 0..127
    const int lk = (tid & 1) * 32;    // halves

    const uint32_t smb = smem_u32(fsm);
    uint32_t dKh[2], dKl[2], dVh[2], dVl[2], dMs[2];
#pragma unroll
    for (int st = 0; st < 2; st++) {
        const uint32_t sb = smb + (uint32_t)(FKV0 + st * FKVSTG + lr * FROW + lk) * 2;
        dKh[st] = sb;
        dKl[st] = sb + 128 * FROW * 2;
        dVh[st] = sb + 2 * 128 * FROW * 2;
        dVl[st] = sb + 3 * 128 * FROW * 2;
        dMs[st] = smb + FMASK_B + st * 512 + (tid & 127) * 4;
    }

    auto prefetchKV = [&](int j, int st) {
        const size_t off = hbase + (size_t)(j * 128 + lr) * HD + lk;
        const __nv_bfloat16* kh = g_kh + off;
        const __nv_bfloat16* kl = g_kl + off;
        const __nv_bfloat16* vh = g_vh + off;
        const __nv_bfloat16* vl = g_vl + off;
#pragma unroll
        for (int q = 0; q < 4; q++) {
            cpa16(dKh[st] + q * 16, kh + q * 8);
            cpa16(dKl[st] + q * 16, kl + q * 8);
            cpa16(dVh[st] + q * 16, vh + q * 8);
            cpa16(dVl[st] + q * 16, vl + q * 8);
        }
        if (tid < 128) cpa4(dMs[st], mrow + j * 128 + tid);
    };

    // ---- Q tile -> smem, hoist fragments ----
    {
        const uint4* qh4 = (const uint4*)(g_qh + hbase + (size_t)(bq + lr) * HD + lk);
        const uint4* ql4 = (const uint4*)(g_ql + hbase + (size_t)(bq + lr) * HD + lk);
        uint4* dh = (uint4*)&sQhi[lr * FROW + lk];
        uint4* dl = (uint4*)&sQlo[lr * FROW + lk];
#pragma unroll
        for (int q = 0; q < 4; q++) { dh[q] = qh4[q]; dl[q] = ql4[q]; }
    }
    prefetchKV(0, 0);
    CP_COMMIT();
    __syncthreads();

    uint32_t qh[4][4], ql[4][4];
    {
        const int ar = w * 16 + (lane & 15);
        const int acb = (lane >> 4) * 8;
#pragma unroll
        for (int kk = 0; kk < 4; kk++) {
            ldm_x4(qh[kk], smem_u32(&sQhi[ar * FROW + kk * 16 + acb]));
            ldm_x4(ql[kk], smem_u32(&sQlo[ar * FROW + kk * 16 + acb]));
        }
    }

    float acco[8][4];
#pragma unroll
    for (int i = 0; i < 8; i++)
#pragma unroll
        for (int t = 0; t < 4; t++) acco[i][t] = 0.f;
    float m0 = -3.4e38f, m1 = -3.4e38f, l0 = 0.f, l1 = 0.f;

    for (int j = 0; j < S / 128; j++) {
        const int st = j & 1;
        CP_WAIT0();
        __syncthreads();
        if (j + 1 < S / 128) { prefetchKV(j + 1, st ^ 1); CP_COMMIT(); }

        const uint16_t* sKhi = smu + FKV0 + st * FKVSTG;
        const uint16_t* sKlo = sKhi + 128 * FROW;
        const uint16_t* sVhi = sKhi + 2 * 128 * FROW;
        const uint16_t* sVlo = sKhi + 3 * 128 * FROW;
        const float* maskS = (const float*)(fsm + FMASK_B + st * 512);

        // ---- S = Q K^T ----
        float accs[16][4];
#pragma unroll
        for (int i = 0; i < 16; i++)
#pragma unroll
            for (int t = 0; t < 4; t++) accs[i][t] = 0.f;

#pragma unroll
        for (int kk = 0; kk < 4; kk++) {
            const int krow = (lane & 7) + ((lane >> 4) & 1) * 8;
            const int kcol = kk * 16 + ((lane >> 3) & 1) * 8;
#pragma unroll
            for (int np = 0; np < 8; np++) {
                uint32_t kh4[4], kl4[4];
                ldm_x4(kh4, smem_u32(&sKhi[(np * 16 + krow) * FROW + kcol]));
                ldm_x4(kl4, smem_u32(&sKlo[(np * 16 + krow) * FROW + kcol]));
                mma_bf16(accs[2*np],   qh[kk], &kh4[0]);
                mma_bf16(accs[2*np],   qh[kk], &kl4[0]);
                mma_bf16(accs[2*np],   ql[kk], &kh4[0]);
                mma_bf16(accs[2*np+1], qh[kk], &kh4[2]);
                mma_bf16(accs[2*np+1], qh[kk], &kl4[2]);
                mma_bf16(accs[2*np+1], ql[kk], &kh4[2]);
            }
        }

        // ---- scale + mask + online softmax ----
        float tmax0 = -3.4e38f, tmax1 = -3.4e38f;
#pragma unroll
        for (int ni = 0; ni < 16; ni++) {
            const int c = ni * 8 + (lane & 3) * 2;
            const float mk0 = maskS[c], mk1 = maskS[c + 1];
            accs[ni][0] = fmaf(accs[ni][0], SCALE, mk0);
            accs[ni][1] = fmaf(accs[ni][1], SCALE, mk1);
            accs[ni][2] = fmaf(accs[ni][2], SCALE, mk0);
            accs[ni][3] = fmaf(accs[ni][3], SCALE, mk1);
            tmax0 = fmaxf(tmax0, fmaxf(accs[ni][0], accs[ni][1]));
            tmax1 = fmaxf(tmax1, fmaxf(accs[ni][2], accs[ni][3]));
        }
        tmax0 = fmaxf(tmax0, __shfl_xor_sync(~0u, tmax0, 1));
        tmax0 = fmaxf(tmax0, __shfl_xor_sync(~0u, tmax0, 2));
        tmax1 = fmaxf(tmax1, __shfl_xor_sync(~0u, tmax1, 1));
        tmax1 = fmaxf(tmax1, __shfl_xor_sync(~0u, tmax1, 2));

        const float mn0 = fmaxf(m0, tmax0);
        const float mn1 = fmaxf(m1, tmax1);
        const float alpha0 = __expf(m0 - mn0);
        const float alpha1 = __expf(m1 - mn1);
        m0 = mn0; m1 = mn1;

        float sum0 = 0.f, sum1 = 0.f;
#pragma unroll
        for (int ni = 0; ni < 16; ni++) {
            accs[ni][0] = __expf(accs[ni][0] - mn0);
            accs[ni][1] = __expf(accs[ni][1] - mn0);
            accs[ni][2] = __expf(accs[ni][2] - mn1);
            accs[ni][3] = __expf(accs[ni][3] - mn1);
            sum0 += accs[ni][0] + accs[ni][1];
            sum1 += accs[ni][2] + accs[ni][3];
        }
        sum0 += __shfl_xor_sync(~0u, sum0, 1);
        sum0 += __shfl_xor_sync(~0u, sum0, 2);
        sum1 += __shfl_xor_sync(~0u, sum1, 1);
        sum1 += __shfl_xor_sync(~0u, sum1, 2);
        l0 = l0 * alpha0 + sum0;
        l1 = l1 * alpha1 + sum1;

#pragma unroll
        for (int ni = 0; ni < 8; ni++) {
            acco[ni][0] *= alpha0; acco[ni][1] *= alpha0;
            acco[ni][2] *= alpha1; acco[ni][3] *= alpha1;
        }

        // ---- O += P V ----
#pragma unroll
        for (int kk = 0; kk < 8; kk++) {
            uint32_t ph[4], pl[4];
            split2(accs[2*kk][0],   accs[2*kk][1],   ph[0], pl[0]);
            split2(accs[2*kk][2],   accs[2*kk][3],   ph[1], pl[1]);
            split2(accs[2*kk+1][0], accs[2*kk+1][1], ph[2], pl[2]);
            split2(accs[2*kk+1][2], accs[2*kk+1][3], ph[3], pl[3]);
            const int vrow = kk * 16 + (lane & 7) + ((lane >> 3) & 1) * 8;
#pragma unroll
            for (int np = 0; np < 4; np++) {
                const int vcol = np * 16 + (lane >> 4) * 8;
                uint32_t vh4[4], vl4[4];
                ldm_x4t(vh4, smem_u32(&sVhi[vrow * FROW + vcol]));
                ldm_x4t(vl4, smem_u32(&sVlo[vrow * FROW + vcol]));
                mma_bf16(acco[2*np],   ph, &vh4[0]);
                mma_bf16(acco[2*np],   ph, &vl4[0]);
                mma_bf16(acco[2*np],   pl, &vh4[0]);
                mma_bf16(acco[2*np+1], ph, &vh4[2]);
                mma_bf16(acco[2*np+1], ph, &vl4[2]);
                mma_bf16(acco[2*np+1], pl, &vh4[2]);
            }
        }
    }

    // ---- finalize ----
    const float inv0 = 1.f / l0;
    const float inv1 = 1.f / l1;
    const int q0 = bq + w * 16 + (lane >> 2);
#pragma unroll
    for (int ni = 0; ni < 8; ni++) {
        const int d = ni * 8 + (lane & 3) * 2;
        const size_t i0 = ((size_t)(b_ * S + q0)) * H + h_ * HD + d;
        const size_t i1 = ((size_t)(b_ * S + q0 + 8)) * H + h_ * HD + d;
        uint32_t hp, lp;
        split2(acco[ni][0] * inv0, acco[ni][1] * inv0, hp, lp);
        *(uint32_t*)&g_ch[i0] = hp;
        *(uint32_t*)&g_cl[i0] = lp;
        split2(acco[ni][2] * inv1, acco[ni][3] * inv1, hp, lp);
        *(uint32_t*)&g_ch[i1] = hp;
        *(uint32_t*)&g_cl[i1] = lp;
    }
}

// ---------------------------------------------------------------------------
// out = LayerNorm(g_proj + hidden) * gamma + beta
// ---------------------------------------------------------------------------
__global__ __launch_bounds__(256, 1)
void add_ln(const float* __restrict__ hidden,
            const float* __restrict__ gamma,
            const float* __restrict__ beta,
            float* __restrict__ out)
{
    const size_t row = blockIdx.x;
    const int tid = threadIdx.x;
    __shared__ float r1[8], r2[8];

    float4 a  = *(const float4*)&g_proj[row * H + tid * 4];
    float4 hv = *(const float4*)&hidden[row * H + tid * 4];
    float x0 = a.x + hv.x, x1 = a.y + hv.y, x2 = a.z + hv.z, x3 = a.w + hv.w;

    float s1 = x0 + x1 + x2 + x3;
    float s2 = fmaf(x0, x0, fmaf(x1, x1, fmaf(x2, x2, x3 * x3)));
#pragma unroll
    for (int o = 16; o; o >>= 1) {
        s1 += __shfl_xor_sync(~0u, s1, o);
        s2 += __shfl_xor_sync(~0u, s2, o);
    }
    if ((tid & 31) == 0) { r1[tid >> 5] = s1; r2[tid >> 5] = s2; }
    __syncthreads();
    float t1 = 0.f, t2 = 0.f;
#pragma unroll
    for (int i = 0; i < 8; i++) { t1 += r1[i]; t2 += r2[i]; }

    const float mu  = t1 * (1.f / H);
    const float var = t2 * (1.f / H) - mu * mu;
    const float inv = rsqrtf(var + LN_EPS);

    float4 g  = *(const float4*)&gamma[tid * 4];
    float4 bt = *(const float4*)&beta[tid * 4];
    float4 o;
    o.x = (x0 - mu) * inv * g.x + bt.x;
    o.y = (x1 - mu) * inv * g.y + bt.y;
    o.z = (x2 - mu) * inv * g.z + bt.z;
    o.w = (x3 - mu) * inv * g.w + bt.w;
    *(float4*)&out[row * H + tid * 4] = o;
}

// ---------------------------------------------------------------------------
extern "C" void kernel_launch(void* const* d_in, const int* in_sizes, int n_in,
                              void* d_out, int out_size)
{
    const float* hidden = (const float*)d_in[0];
    const float* mask   = (const float*)d_in[1];
    const float* Wq     = (const float*)d_in[2];
    const float* bq     = (const float*)d_in[3];
    const float* Wk     = (const float*)d_in[4];
    const float* bk     = (const float*)d_in[5];
    const float* Wv     = (const float*)d_in[6];
    const float* bv     = (const float*)d_in[7];
    const float* Wo     = (const float*)d_in[8];
    const float* bo     = (const float*)d_in[9];
    const float* gamma  = (const float*)d_in[10];
    const float* beta   = (const float*)d_in[11];
    float* out          = (float*)d_out;

    cudaFuncSetAttribute(gemm_bf16, cudaFuncAttributeMaxDynamicSharedMemorySize,
                         GEMM_SMEM);
    cudaFuncSetAttribute(flash_attn, cudaFuncAttributeMaxDynamicSharedMemorySize,
                         FLASH_SMEM);

    dim3 blk(256);
    cvt_split<<<(M * H) / 1024, blk>>>(hidden, 0);
    cvt_split<<<(H * H) / 1024, blk>>>(Wq, 1);
    cvt_split<<<(H * H) / 1024, blk>>>(Wk, 2);
    cvt_split<<<(H * H) / 1024, blk>>>(Wv, 3);
    cvt_split<<<(H * H) / 1024, blk>>>(Wo, 4);

    dim3 gqkv(H / 128, M / 128);        // (8, 64)
    gemm_bf16<<<gqkv, blk, GEMM_SMEM>>>(bq, 0);
    gemm_bf16<<<gqkv, blk, GEMM_SMEM>>>(bk, 1);
    gemm_bf16<<<gqkv, blk, GEMM_SMEM>>>(bv, 2);

    dim3 gfa(S / 128, BH);              // (8, 128)
    flash_attn<<<gfa, blk, FLASH_SMEM>>>(mask);

    gemm_bf16<<<gqkv, blk, GEMM_SMEM>>>(bo, 3);

    add_ln<<<M, blk>>>(hidden, gamma, beta, out);
}

// round 7
// speedup vs baseline: 1.0943x; 1.0943x over previous
#include <cuda_runtime.h>
#include <cuda_bf16.h>
#include <cstdint>

namespace {
constexpr int B  = 8;
constexpr int S  = 1024;
constexpr int H  = 1024;
constexpr int NH = 16;
constexpr int HD = 64;
constexpr int M  = B * S;    // 8192
constexpr int BH = B * NH;   // 128
constexpr float SCALE  = 0.125f;
constexpr float LN_EPS = 1e-12f;
constexpr int BK = 32;

// GEMM smem (u16 units): 2 stages x (Ahi,Alo,Bhi,Blo each 128x40)
constexpr int GARR = 128 * 40;          // 5120 u16
constexpr int GSTG = 4 * GARR;          // 20480 u16
constexpr int GEMM_SMEM = 2 * GSTG * 2; // 81920 bytes

// flash smem (u16 units, row stride 72) — R5 layout
constexpr int FROW = 72;
constexpr int FQ_HI = 0;
constexpr int FQ_LO = 128 * FROW;
constexpr int FK_HI = 2 * 128 * FROW;
constexpr int FK_LO = 3 * 128 * FROW;
constexpr int FV_HI = 4 * 128 * FROW;
constexpr int FV_LO = 5 * 128 * FROW;
constexpr int FLASH_U16  = 6 * 128 * FROW;
constexpr int FLASH_SMEM = FLASH_U16 * 2 + 512;
}

// ---------------------------------------------------------------------------
// Scratch (allocation-free: __device__ globals)
// ---------------------------------------------------------------------------
__device__ __nv_bfloat16 g_hh[M * H],  g_hl[M * H];
__device__ __nv_bfloat16 g_wh[4u * H * H], g_wl[4u * H * H];
__device__ __nv_bfloat16 g_qh[BH*S*HD], g_ql[BH*S*HD];
__device__ __nv_bfloat16 g_kh[BH*S*HD], g_kl[BH*S*HD];
__device__ __nv_bfloat16 g_vh[BH*S*HD], g_vl[BH*S*HD];
__device__ __nv_bfloat16 g_ch[M * H],  g_cl[M * H];
__device__ float g_proj[M * H];

// ---------------------------------------------------------------------------
// helpers
// ---------------------------------------------------------------------------
__device__ __forceinline__ uint32_t smem_u32(const void* p) {
    uint32_t a;
    asm("{ .reg .u64 t; cvta.to.shared.u64 t, %1; cvt.u32.u64 %0, t; }"
        : "=r"(a) : "l"(p));
    return a;
}
__device__ __forceinline__ void mma_bf16(float* c, const uint32_t* a, const uint32_t* b) {
    asm volatile(
        "mma.sync.aligned.m16n8k16.row.col.f32.bf16.bf16.f32 "
        "{%0,%1,%2,%3}, {%4,%5,%6,%7}, {%8,%9}, {%0,%1,%2,%3};"
        : "+f"(c[0]), "+f"(c[1]), "+f"(c[2]), "+f"(c[3])
        : "r"(a[0]), "r"(a[1]), "r"(a[2]), "r"(a[3]), "r"(b[0]), "r"(b[1]));
}
__device__ __forceinline__ void ldm_x4(uint32_t* r, uint32_t addr) {
    asm volatile("ldmatrix.sync.aligned.m8n8.x4.shared.b16 {%0,%1,%2,%3}, [%4];"
                 : "=r"(r[0]), "=r"(r[1]), "=r"(r[2]), "=r"(r[3]) : "r"(addr));
}
__device__ __forceinline__ void ldm_x4t(uint32_t* r, uint32_t addr) {
    asm volatile("ldmatrix.sync.aligned.m8n8.x4.trans.shared.b16 {%0,%1,%2,%3}, [%4];"
                 : "=r"(r[0]), "=r"(r[1]), "=r"(r[2]), "=r"(r[3]) : "r"(addr));
}
__device__ __forceinline__ void split2(float x, float y, uint32_t& hi, uint32_t& lo) {
    asm("cvt.rn.bf16x2.f32 %0, %1, %2;" : "=r"(hi) : "f"(y), "f"(x));
    float hx = __uint_as_float(hi << 16);
    float hy = __uint_as_float(hi & 0xFFFF0000u);
    float rx = x - hx;
    float ry = y - hy;
    asm("cvt.rn.bf16x2.f32 %0, %1, %2;" : "=r"(lo) : "f"(ry), "f"(rx));
}

// ---------------------------------------------------------------------------
// One-time fp32 -> hi/lo bf16 split.
// ---------------------------------------------------------------------------
__global__ __launch_bounds__(256, 8)
void cvt_split(const float* __restrict__ src, int sel)
{
    __nv_bfloat16* hi = (sel == 0) ? g_hh : g_wh + (size_t)(sel - 1) * H * H;
    __nv_bfloat16* lo = (sel == 0) ? g_hl : g_wl + (size_t)(sel - 1) * H * H;
    const size_t i = ((size_t)blockIdx.x * 256 + threadIdx.x) * 4;
    float4 f = *(const float4*)&src[i];
    uint32_t h0, l0, h1, l1;
    split2(f.x, f.y, h0, l0);
    split2(f.z, f.w, h1, l1);
    *(uint2*)&hi[i] = make_uint2(h0, h1);
    *(uint2*)&lo[i] = make_uint2(l0, l1);
}

// ---------------------------------------------------------------------------
// bf16 GEMM: C = X @ W^T + bias.  128x128 tile, 512 threads / 16 warps,
// 32x32 warp tiles (4 warps per SMSP for latency hiding).
// Double-buffered smem, ONE __syncthreads per K-slab.
// dst_sel 0/1/2 -> q/k/v hi/lo headsplit; 3 -> g_proj fp32 (X := ctx hi/lo)
// ---------------------------------------------------------------------------
__global__ __launch_bounds__(512, 1)
void gemm_bf16(const float* __restrict__ bias, int dst_sel)
{
    extern __shared__ __align__(16) char gsm[];
    uint16_t* smu = (uint16_t*)gsm;

    const bool headsplit = dst_sel < 3;
    const __nv_bfloat16* Xhi = headsplit ? g_hh : g_ch;
    const __nv_bfloat16* Xlo = headsplit ? g_hl : g_cl;
    const __nv_bfloat16* Whi = g_wh + (size_t)dst_sel * H * H;
    const __nv_bfloat16* Wlo = g_wl + (size_t)dst_sel * H * H;
    __nv_bfloat16* dhi = (dst_sel == 0) ? g_qh : (dst_sel == 1) ? g_kh : g_vh;
    __nv_bfloat16* dlo = (dst_sel == 0) ? g_ql : (dst_sel == 1) ? g_kl : g_vl;

    const int tid  = threadIdx.x;
    const int lane = tid & 31;
    const int wid  = tid >> 5;           // 0..15
    const int bm   = blockIdx.y * 128;
    const int bn   = blockIdx.x * 128;
    const int m_off = (wid & 3) * 32;
    const int n_off = (wid >> 2) * 32;

    // loaders: 512 threads cover 128 rows x 32 halves, 1 uint4 per array each
    const int lr = tid >> 2;             // 0..127
    const int lk = (tid & 3) * 8;        // halves
    const uint4* xh = (const uint4*)(Xhi + (size_t)(bm + lr) * H);
    const uint4* xl = (const uint4*)(Xlo + (size_t)(bm + lr) * H);
    const uint4* wh = (const uint4*)(Whi + (size_t)(bn + lr) * H);
    const uint4* wl = (const uint4*)(Wlo + (size_t)(bn + lr) * H);
    const int lq = lk >> 3;              // uint4 index within slab

    uint4 rAh, rAl, rBh, rBl;
    auto loadg = [&](int s) {
        const int o = s * 4 + lq;
        rAh = xh[o]; rAl = xl[o];
        rBh = wh[o]; rBl = wl[o];
    };
    auto stores = [&](int st) {
        uint16_t* base = smu + st * GSTG;
        *(uint4*)&base[lr * 40 + lk]            = rAh;
        *(uint4*)&base[GARR + lr * 40 + lk]     = rAl;
        *(uint4*)&base[2 * GARR + lr * 40 + lk] = rBh;
        *(uint4*)&base[3 * GARR + lr * 40 + lk] = rBl;
    };

    float acc[2][4][4];
#pragma unroll
    for (int i = 0; i < 2; i++)
#pragma unroll
        for (int j = 0; j < 4; j++)
#pragma unroll
            for (int t = 0; t < 4; t++) acc[i][j][t] = 0.f;

    loadg(0);
    stores(0);
    __syncthreads();

    const int NS = H / BK;  // 32
    for (int s = 0; s < NS; s++) {
        const int st = s & 1;
        if (s + 1 < NS) loadg(s + 1);

        const uint16_t* Ahi = smu + st * GSTG;
        const uint16_t* Alo = Ahi + GARR;
        const uint16_t* Bhi = Ahi + 2 * GARR;
        const uint16_t* Blo = Ahi + 3 * GARR;

#pragma unroll
        for (int kk = 0; kk < 2; kk++) {
            const int kel = kk * 16;
            uint32_t ah[2][4], al[2][4], bh[2][4], bl[2][4];
            const int ar = m_off + (lane & 15);
            const int ac = kel + (lane >> 4) * 8;
#pragma unroll
            for (int mi = 0; mi < 2; mi++) {
                ldm_x4(ah[mi], smem_u32(&Ahi[(ar + mi * 16) * 40 + ac]));
                ldm_x4(al[mi], smem_u32(&Alo[(ar + mi * 16) * 40 + ac]));
            }
            const int br = n_off + (lane & 7) + ((lane >> 4) & 1) * 8;
            const int bc = kel + ((lane >> 3) & 1) * 8;
#pragma unroll
            for (int np = 0; np < 2; np++) {
                ldm_x4(bh[np], smem_u32(&Bhi[(br + np * 16) * 40 + bc]));
                ldm_x4(bl[np], smem_u32(&Blo[(br + np * 16) * 40 + bc]));
            }
#pragma unroll
            for (int mi = 0; mi < 2; mi++)
#pragma unroll
                for (int np = 0; np < 2; np++)
#pragma unroll
                    for (int half = 0; half < 2; half++) {
                        const int ni = np * 2 + half;
                        const uint32_t* bhp = &bh[np][half * 2];
                        const uint32_t* blp = &bl[np][half * 2];
                        mma_bf16(acc[mi][ni], ah[mi], bhp);
                        mma_bf16(acc[mi][ni], ah[mi], blp);
                        mma_bf16(acc[mi][ni], al[mi], bhp);
                    }
        }
        if (s + 1 < NS) stores(st ^ 1);
        __syncthreads();
    }

#pragma unroll
    for (int mi = 0; mi < 2; mi++) {
#pragma unroll
        for (int ni = 0; ni < 4; ni++) {
            const int col = bn + n_off + ni * 8 + (lane & 3) * 2;
            const float2 bs = *(const float2*)&bias[col];
#pragma unroll
            for (int h2 = 0; h2 < 2; h2++) {
                const int row = bm + m_off + mi * 16 + (lane >> 2) + h2 * 8;
                float vx = acc[mi][ni][h2 * 2 + 0] + bs.x;
                float vy = acc[mi][ni][h2 * 2 + 1] + bs.y;
                if (headsplit) {
                    const int b_ = row >> 10, s_ = row & 1023;
                    const int h_ = col >> 6,  d_ = col & 63;
                    const size_t idx = ((size_t)(b_ * NH + h_) * S + s_) * HD + d_;
                    uint32_t hp, lp;
                    split2(vx, vy, hp, lp);
                    *(uint32_t*)&dhi[idx] = hp;
                    *(uint32_t*)&dlo[idx] = lp;
                } else {
                    float2 v; v.x = vx; v.y = vy;
                    *(float2*)&g_proj[(size_t)row * H + col] = v;
                }
            }
        }
    }
}

// ---------------------------------------------------------------------------
// Flash attention (R5 version). Block = (q-tile 128, head); 8 warps.
// ---------------------------------------------------------------------------
__global__ __launch_bounds__(256, 1)
void flash_attn(const float* __restrict__ mask)
{
    extern __shared__ __align__(16) char fsm[];
    uint16_t* sQhi = (uint16_t*)fsm + FQ_HI;
    uint16_t* sQlo = (uint16_t*)fsm + FQ_LO;
    uint16_t* sKhi = (uint16_t*)fsm + FK_HI;
    uint16_t* sKlo = (uint16_t*)fsm + FK_LO;
    uint16_t* sVhi = (uint16_t*)fsm + FV_HI;
    uint16_t* sVlo = (uint16_t*)fsm + FV_LO;
    float*    maskS = (float*)(fsm + FLASH_U16 * 2);

    const int head = blockIdx.y;
    const int b_   = head >> 4;
    const int h_   = head & 15;
    const size_t hbase = (size_t)head * S * HD;
    const float* mrow = mask + (size_t)b_ * S;

    const int tid  = threadIdx.x;
    const int lane = tid & 31;
    const int w    = tid >> 5;
    const int bq   = blockIdx.x * 128;

    const int lr = tid >> 1;
    const int lk = (tid & 1) * 32;

    {
        const uint4* qh4 = (const uint4*)(g_qh + hbase + (size_t)(bq + lr) * HD + lk);
        const uint4* ql4 = (const uint4*)(g_ql + hbase + (size_t)(bq + lr) * HD + lk);
        uint4* dh = (uint4*)&sQhi[lr * FROW + lk];
        uint4* dl = (uint4*)&sQlo[lr * FROW + lk];
#pragma unroll
        for (int q = 0; q < 4; q++) { dh[q] = qh4[q]; dl[q] = ql4[q]; }
    }
    __syncthreads();

    uint32_t qh[4][4], ql[4][4];
    {
        const int ar = w * 16 + (lane & 15);
        const int acb = (lane >> 4) * 8;
#pragma unroll
        for (int kk = 0; kk < 4; kk++) {
            ldm_x4(qh[kk], smem_u32(&sQhi[ar * FROW + kk * 16 + acb]));
            ldm_x4(ql[kk], smem_u32(&sQlo[ar * FROW + kk * 16 + acb]));
        }
    }

    float acco[8][4];
#pragma unroll
    for (int i = 0; i < 8; i++)
#pragma unroll
        for (int t = 0; t < 4; t++) acco[i][t] = 0.f;
    float m0 = -3.4e38f, m1 = -3.4e38f, l0 = 0.f, l1 = 0.f;

    for (int j = 0; j < S / 128; j++) {
        __syncthreads();
        {
            const size_t off = hbase + (size_t)(j * 128 + lr) * HD + lk;
            const uint4* kh4 = (const uint4*)(g_kh + off);
            const uint4* kl4 = (const uint4*)(g_kl + off);
            const uint4* vh4 = (const uint4*)(g_vh + off);
            const uint4* vl4 = (const uint4*)(g_vl + off);
            uint4* dkh = (uint4*)&sKhi[lr * FROW + lk];
            uint4* dkl = (uint4*)&sKlo[lr * FROW + lk];
            uint4* dvh = (uint4*)&sVhi[lr * FROW + lk];
            uint4* dvl = (uint4*)&sVlo[lr * FROW + lk];
#pragma unroll
            for (int q = 0; q < 4; q++) {
                dkh[q] = kh4[q]; dkl[q] = kl4[q];
                dvh[q] = vh4[q]; dvl[q] = vl4[q];
            }
            if (tid < 128) maskS[tid] = mrow[j * 128 + tid];
        }
        __syncthreads();

        float accs[16][4];
#pragma unroll
        for (int i = 0; i < 16; i++)
#pragma unroll
            for (int t = 0; t < 4; t++) accs[i][t] = 0.f;

#pragma unroll
        for (int kk = 0; kk < 4; kk++) {
            const int krow = (lane & 7) + ((lane >> 4) & 1) * 8;
            const int kcol = kk * 16 + ((lane >> 3) & 1) * 8;
#pragma unroll
            for (int np = 0; np < 8; np++) {
                uint32_t kh4[4], kl4[4];
                ldm_x4(kh4, smem_u32(&sKhi[(np * 16 + krow) * FROW + kcol]));
                ldm_x4(kl4, smem_u32(&sKlo[(np * 16 + krow) * FROW + kcol]));
                mma_bf16(accs[2*np],   qh[kk], &kh4[0]);
                mma_bf16(accs[2*np],   qh[kk], &kl4[0]);
                mma_bf16(accs[2*np],   ql[kk], &kh4[0]);
                mma_bf16(accs[2*np+1], qh[kk], &kh4[2]);
                mma_bf16(accs[2*np+1], qh[kk], &kl4[2]);
                mma_bf16(accs[2*np+1], ql[kk], &kh4[2]);
            }
        }

        float tmax0 = -3.4e38f, tmax1 = -3.4e38f;
#pragma unroll
        for (int ni = 0; ni < 16; ni++) {
            const int c = ni * 8 + (lane & 3) * 2;
            const float mk0 = maskS[c], mk1 = maskS[c + 1];
            accs[ni][0] = fmaf(accs[ni][0], SCALE, mk0);
            accs[ni][1] = fmaf(accs[ni][1], SCALE, mk1);
            accs[ni][2] = fmaf(accs[ni][2], SCALE, mk0);
            accs[ni][3] = fmaf(accs[ni][3], SCALE, mk1);
            tmax0 = fmaxf(tmax0, fmaxf(accs[ni][0], accs[ni][1]));
            tmax1 = fmaxf(tmax1, fmaxf(accs[ni][2], accs[ni][3]));
        }
        tmax0 = fmaxf(tmax0, __shfl_xor_sync(~0u, tmax0, 1));
        tmax0 = fmaxf(tmax0, __shfl_xor_sync(~0u, tmax0, 2));
        tmax1 = fmaxf(tmax1, __shfl_xor_sync(~0u, tmax1, 1));
        tmax1 = fmaxf(tmax1, __shfl_xor_sync(~0u, tmax1, 2));

        const float mn0 = fmaxf(m0, tmax0);
        const float mn1 = fmaxf(m1, tmax1);
        const float alpha0 = __expf(m0 - mn0);
        const float alpha1 = __expf(m1 - mn1);
        m0 = mn0; m1 = mn1;

        float sum0 = 0.f, sum1 = 0.f;
#pragma unroll
        for (int ni = 0; ni < 16; ni++) {
            accs[ni][0] = __expf(accs[ni][0] - mn0);
            accs[ni][1] = __expf(accs[ni][1] - mn0);
            accs[ni][2] = __expf(accs[ni][2] - mn1);
            accs[ni][3] = __expf(accs[ni][3] - mn1);
            sum0 += accs[ni][0] + accs[ni][1];
            sum1 += accs[ni][2] + accs[ni][3];
        }
        sum0 += __shfl_xor_sync(~0u, sum0, 1);
        sum0 += __shfl_xor_sync(~0u, sum0, 2);
        sum1 += __shfl_xor_sync(~0u, sum1, 1);
        sum1 += __shfl_xor_sync(~0u, sum1, 2);
        l0 = l0 * alpha0 + sum0;
        l1 = l1 * alpha1 + sum1;

#pragma unroll
        for (int ni = 0; ni < 8; ni++) {
            acco[ni][0] *= alpha0; acco[ni][1] *= alpha0;
            acco[ni][2] *= alpha1; acco[ni][3] *= alpha1;
        }

#pragma unroll
        for (int kk = 0; kk < 8; kk++) {
            uint32_t ph[4], pl[4];
            split2(accs[2*kk][0],   accs[2*kk][1],   ph[0], pl[0]);
            split2(accs[2*kk][2],   accs[2*kk][3],   ph[1], pl[1]);
            split2(accs[2*kk+1][0], accs[2*kk+1][1], ph[2], pl[2]);
            split2(accs[2*kk+1][2], accs[2*kk+1][3], ph[3], pl[3]);
            const int vrow = kk * 16 + (lane & 7) + ((lane >> 3) & 1) * 8;
#pragma unroll
            for (int np = 0; np < 4; np++) {
                const int vcol = np * 16 + (lane >> 4) * 8;
                uint32_t vh4[4], vl4[4];
                ldm_x4t(vh4, smem_u32(&sVhi[vrow * FROW + vcol]));
                ldm_x4t(vl4, smem_u32(&sVlo[vrow * FROW + vcol]));
                mma_bf16(acco[2*np],   ph, &vh4[0]);
                mma_bf16(acco[2*np],   ph, &vl4[0]);
                mma_bf16(acco[2*np],   pl, &vh4[0]);
                mma_bf16(acco[2*np+1], ph, &vh4[2]);
                mma_bf16(acco[2*np+1], ph, &vl4[2]);
                mma_bf16(acco[2*np+1], pl, &vh4[2]);
            }
        }
    }

    const float inv0 = 1.f / l0;
    const float inv1 = 1.f / l1;
    const int q0 = bq + w * 16 + (lane >> 2);
#pragma unroll
    for (int ni = 0; ni < 8; ni++) {
        const int d = ni * 8 + (lane & 3) * 2;
        const size_t i0 = ((size_t)(b_ * S + q0)) * H + h_ * HD + d;
        const size_t i1 = ((size_t)(b_ * S + q0 + 8)) * H + h_ * HD + d;
        uint32_t hp, lp;
        split2(acco[ni][0] * inv0, acco[ni][1] * inv0, hp, lp);
        *(uint32_t*)&g_ch[i0] = hp;
        *(uint32_t*)&g_cl[i0] = lp;
        split2(acco[ni][2] * inv1, acco[ni][3] * inv1, hp, lp);
        *(uint32_t*)&g_ch[i1] = hp;
        *(uint32_t*)&g_cl[i1] = lp;
    }
}

// ---------------------------------------------------------------------------
// out = LayerNorm(g_proj + hidden) * gamma + beta
// ---------------------------------------------------------------------------
__global__ __launch_bounds__(256, 1)
void add_ln(const float* __restrict__ hidden,
            const float* __restrict__ gamma,
            const float* __restrict__ beta,
            float* __restrict__ out)
{
    const size_t row = blockIdx.x;
    const int tid = threadIdx.x;
    __shared__ float r1[8], r2[8];

    float4 a  = *(const float4*)&g_proj[row * H + tid * 4];
    float4 hv = *(const float4*)&hidden[row * H + tid * 4];
    float x0 = a.x + hv.x, x1 = a.y + hv.y, x2 = a.z + hv.z, x3 = a.w + hv.w;

    float s1 = x0 + x1 + x2 + x3;
    float s2 = fmaf(x0, x0, fmaf(x1, x1, fmaf(x2, x2, x3 * x3)));
#pragma unroll
    for (int o = 16; o; o >>= 1) {
        s1 += __shfl_xor_sync(~0u, s1, o);
        s2 += __shfl_xor_sync(~0u, s2, o);
    }
    if ((tid & 31) == 0) { r1[tid >> 5] = s1; r2[tid >> 5] = s2; }
    __syncthreads();
    float t1 = 0.f, t2 = 0.f;
#pragma unroll
    for (int i = 0; i < 8; i++) { t1 += r1[i]; t2 += r2[i]; }

    const float mu  = t1 * (1.f / H);
    const float var = t2 * (1.f / H) - mu * mu;
    const float inv = rsqrtf(var + LN_EPS);

    float4 g  = *(const float4*)&gamma[tid * 4];
    float4 bt = *(const float4*)&beta[tid * 4];
    float4 o;
    o.x = (x0 - mu) * inv * g.x + bt.x;
    o.y = (x1 - mu) * inv * g.y + bt.y;
    o.z = (x2 - mu) * inv * g.z + bt.z;
    o.w = (x3 - mu) * inv * g.w + bt.w;
    *(float4*)&out[row * H + tid * 4] = o;
}

// ---------------------------------------------------------------------------
extern "C" void kernel_launch(void* const* d_in, const int* in_sizes, int n_in,
                              void* d_out, int out_size)
{
    const float* hidden = (const float*)d_in[0];
    const float* mask   = (const float*)d_in[1];
    const float* Wq     = (const float*)d_in[2];
    const float* bq     = (const float*)d_in[3];
    const float* Wk     = (const float*)d_in[4];
    const float* bk     = (const float*)d_in[5];
    const float* Wv     = (const float*)d_in[6];
    const float* bv     = (const float*)d_in[7];
    const float* Wo     = (const float*)d_in[8];
    const float* bo     = (const float*)d_in[9];
    const float* gamma  = (const float*)d_in[10];
    const float* beta   = (const float*)d_in[11];
    float* out          = (float*)d_out;

    cudaFuncSetAttribute(gemm_bf16, cudaFuncAttributeMaxDynamicSharedMemorySize,
                         GEMM_SMEM);
    cudaFuncSetAttribute(flash_attn, cudaFuncAttributeMaxDynamicSharedMemorySize,
                         FLASH_SMEM);

    dim3 blk(256);
    cvt_split<<<(M * H) / 1024, blk>>>(hidden, 0);
    cvt_split<<<(H * H) / 1024, blk>>>(Wq, 1);
    cvt_split<<<(H * H) / 1024, blk>>>(Wk, 2);
    cvt_split<<<(H * H) / 1024, blk>>>(Wv, 3);
    cvt_split<<<(H * H) / 1024, blk>>>(Wo, 4);

    dim3 gqkv(H / 128, M / 128);        // (8, 64)
    gemm_bf16<<<gqkv, 512, GEMM_SMEM>>>(bq, 0);
    gemm_bf16<<<gqkv, 512, GEMM_SMEM>>>(bk, 1);
    gemm_bf16<<<gqkv, 512, GEMM_SMEM>>>(bv, 2);

    dim3 gfa(S / 128, BH);              // (8, 128)
    flash_attn<<<gfa, blk, FLASH_SMEM>>>(mask);

    gemm_bf16<<<gqkv, 512, GEMM_SMEM>>>(bo, 3);

    add_ln<<<M, blk>>>(hidden, gamma, beta, out);
}

// round 8
// speedup vs baseline: 1.1040x; 1.0088x over previous
#include <cuda_runtime.h>
#include <cuda_bf16.h>
#include <cstdint>

namespace {
constexpr int B  = 8;
constexpr int S  = 1024;
constexpr int H  = 1024;
constexpr int NH = 16;
constexpr int HD = 64;
constexpr int M  = B * S;    // 8192
constexpr int BH = B * NH;   // 128
constexpr float SCALE  = 0.125f;
constexpr float LN_EPS = 1e-12f;

// tf32 GEMM smem (fp32 units): 2 stages x (A 128x36 + B 128x36)
constexpr int TBK  = 32;            // fp32 K per slab
constexpr int TST  = 36;            // row stride (fp32), conflict-free for LDSM
constexpr int TARR = 128 * TST;     // 4608 fp32 per array
constexpr int TSTG = 2 * TARR;      // A+B per stage
constexpr int GEMM_SMEM = 2 * TSTG * 4;   // 73728 bytes

// flash smem (u16 units, row stride 72) — R5 layout
constexpr int FROW = 72;
constexpr int FQ_HI = 0;
constexpr int FQ_LO = 128 * FROW;
constexpr int FK_HI = 2 * 128 * FROW;
constexpr int FK_LO = 3 * 128 * FROW;
constexpr int FV_HI = 4 * 128 * FROW;
constexpr int FV_LO = 5 * 128 * FROW;
constexpr int FLASH_U16  = 6 * 128 * FROW;
constexpr int FLASH_SMEM = FLASH_U16 * 2 + 512;
}

// ---------------------------------------------------------------------------
// Scratch (allocation-free: __device__ globals)
// ---------------------------------------------------------------------------
__device__ float g_ht[M * H];            // hidden, tf32-rounded
__device__ float g_wt[4u * H * H];       // Wq,Wk,Wv,Wo tf32-rounded
__device__ __nv_bfloat16 g_qh[BH*S*HD], g_ql[BH*S*HD];
__device__ __nv_bfloat16 g_kh[BH*S*HD], g_kl[BH*S*HD];
__device__ __nv_bfloat16 g_vh[BH*S*HD], g_vl[BH*S*HD];
__device__ float g_ct[M * H];            // ctx, tf32-rounded
__device__ float g_proj[M * H];

// ---------------------------------------------------------------------------
// helpers
// ---------------------------------------------------------------------------
__device__ __forceinline__ uint32_t smem_u32(const void* p) {
    uint32_t a;
    asm("{ .reg .u64 t; cvta.to.shared.u64 t, %1; cvt.u32.u64 %0, t; }"
        : "=r"(a) : "l"(p));
    return a;
}
__device__ __forceinline__ void mma_bf16(float* c, const uint32_t* a, const uint32_t* b) {
    asm volatile(
        "mma.sync.aligned.m16n8k16.row.col.f32.bf16.bf16.f32 "
        "{%0,%1,%2,%3}, {%4,%5,%6,%7}, {%8,%9}, {%0,%1,%2,%3};"
        : "+f"(c[0]), "+f"(c[1]), "+f"(c[2]), "+f"(c[3])
        : "r"(a[0]), "r"(a[1]), "r"(a[2]), "r"(a[3]), "r"(b[0]), "r"(b[1]));
}
__device__ __forceinline__ void mma_tf32(float* c, const uint32_t* a, const uint32_t* b) {
    asm volatile(
        "mma.sync.aligned.m16n8k8.row.col.f32.tf32.tf32.f32 "
        "{%0,%1,%2,%3}, {%4,%5,%6,%7}, {%8,%9}, {%0,%1,%2,%3};"
        : "+f"(c[0]), "+f"(c[1]), "+f"(c[2]), "+f"(c[3])
        : "r"(a[0]), "r"(a[1]), "r"(a[2]), "r"(a[3]), "r"(b[0]), "r"(b[1]));
}
__device__ __forceinline__ void ldm_x4(uint32_t* r, uint32_t addr) {
    asm volatile("ldmatrix.sync.aligned.m8n8.x4.shared.b16 {%0,%1,%2,%3}, [%4];"
                 : "=r"(r[0]), "=r"(r[1]), "=r"(r[2]), "=r"(r[3]) : "r"(addr));
}
__device__ __forceinline__ void ldm_x4t(uint32_t* r, uint32_t addr) {
    asm volatile("ldmatrix.sync.aligned.m8n8.x4.trans.shared.b16 {%0,%1,%2,%3}, [%4];"
                 : "=r"(r[0]), "=r"(r[1]), "=r"(r[2]), "=r"(r[3]) : "r"(addr));
}
__device__ __forceinline__ void split2(float x, float y, uint32_t& hi, uint32_t& lo) {
    asm("cvt.rn.bf16x2.f32 %0, %1, %2;" : "=r"(hi) : "f"(y), "f"(x));
    float hx = __uint_as_float(hi << 16);
    float hy = __uint_as_float(hi & 0xFFFF0000u);
    float rx = x - hx;
    float ry = y - hy;
    asm("cvt.rn.bf16x2.f32 %0, %1, %2;" : "=r"(lo) : "f"(ry), "f"(rx));
}
__device__ __forceinline__ float to_tf32(float x) {
    float y;
    asm("cvt.rna.tf32.f32 %0, %1;" : "=f"(y) : "f"(x));
    return y;
}

// ---------------------------------------------------------------------------
// One-time fp32 -> tf32 rounding. sel 0 -> hidden, 1..4 -> weight slot.
// ---------------------------------------------------------------------------
__global__ __launch_bounds__(256, 8)
void cvt_tf32(const float* __restrict__ src, int sel)
{
    float* dst = (sel == 0) ? g_ht : g_wt + (size_t)(sel - 1) * H * H;
    const size_t i = ((size_t)blockIdx.x * 256 + threadIdx.x) * 4;
    float4 f = *(const float4*)&src[i];
    f.x = to_tf32(f.x); f.y = to_tf32(f.y);
    f.z = to_tf32(f.z); f.w = to_tf32(f.w);
    *(float4*)&dst[i] = f;
}

// ---------------------------------------------------------------------------
// tf32 GEMM: C = X @ W^T + bias.  128x128 tile, 256 threads / 8 warps,
// 64x32 warp tiles, single-pass tf32 (m16n8k8). Double-buffered smem.
// dst_sel 0/1/2 -> q/k/v bf16 hi/lo headsplit; 3 -> g_proj fp32 (X := g_ct)
// ---------------------------------------------------------------------------
__global__ __launch_bounds__(256, 1)
void gemm_tf32(const float* __restrict__ bias, int dst_sel)
{
    extern __shared__ __align__(16) float gsm[];

    const bool headsplit = dst_sel < 3;
    const float* X = headsplit ? g_ht : g_ct;
    const float* W = g_wt + (size_t)dst_sel * H * H;
    __nv_bfloat16* dhi = (dst_sel == 0) ? g_qh : (dst_sel == 1) ? g_kh : g_vh;
    __nv_bfloat16* dlo = (dst_sel == 0) ? g_ql : (dst_sel == 1) ? g_kl : g_vl;

    const int tid  = threadIdx.x;
    const int lane = tid & 31;
    const int wid  = tid >> 5;
    const int bm   = blockIdx.y * 128;
    const int bn   = blockIdx.x * 128;
    const int m_off = (wid & 1) * 64;
    const int n_off = (wid >> 1) * 32;

    // loaders: 2 threads per row; each copies 16 fp32 (4 float4) per array
    const int lr = tid >> 1;             // 0..127
    const int lc = (tid & 1) * 16;       // fp32 col within slab
    const float4* xg = (const float4*)(X + (size_t)(bm + lr) * H + lc);
    const float4* wg = (const float4*)(W + (size_t)(bn + lr) * H + lc);

    float4 rA[4], rB[4];
    auto loadg = [&](int s) {
        const int o = s * 8;  // 32 fp32 = 8 float4 per row per slab
#pragma unroll
        for (int q = 0; q < 4; q++) { rA[q] = xg[o + q]; rB[q] = wg[o + q]; }
    };
    auto stores = [&](int st) {
        float* sA = gsm + st * TSTG;
        float* sB = sA + TARR;
#pragma unroll
        for (int q = 0; q < 4; q++) {
            *(float4*)&sA[lr * TST + lc + q * 4] = rA[q];
            *(float4*)&sB[lr * TST + lc + q * 4] = rB[q];
        }
    };

    float acc[4][4][4];
#pragma unroll
    for (int i = 0; i < 4; i++)
#pragma unroll
        for (int j = 0; j < 4; j++)
#pragma unroll
            for (int t = 0; t < 4; t++) acc[i][j][t] = 0.f;

    loadg(0);
    stores(0);
    __syncthreads();

    const int NS = H / TBK;  // 32
    for (int s = 0; s < NS; s++) {
        const int st = s & 1;
        if (s + 1 < NS) loadg(s + 1);

        const float* sA = gsm + st * TSTG;
        const float* sB = sA + TARR;

#pragma unroll
        for (int kk = 0; kk < 4; kk++) {          // 4 x k8 per slab
            uint32_t a[4][4], b2[2][4];
            const int arow = m_off + (lane & 15);
            const int acol = kk * 8 + (lane >> 4) * 4;
#pragma unroll
            for (int mi = 0; mi < 4; mi++)
                ldm_x4(a[mi], smem_u32(&sA[(arow + mi * 16) * TST + acol]));
            const int brow = n_off + (lane & 7) + ((lane >> 4) & 1) * 8;
            const int bcol = kk * 8 + ((lane >> 3) & 1) * 4;
#pragma unroll
            for (int g = 0; g < 2; g++)
                ldm_x4(b2[g], smem_u32(&sB[(brow + g * 16) * TST + bcol]));
#pragma unroll
            for (int mi = 0; mi < 4; mi++)
#pragma unroll
                for (int g = 0; g < 2; g++)
#pragma unroll
                    for (int h = 0; h < 2; h++)
                        mma_tf32(acc[mi][g * 2 + h], a[mi], &b2[g][h * 2]);
        }
        if (s + 1 < NS) stores(st ^ 1);
        __syncthreads();
    }

#pragma unroll
    for (int mi = 0; mi < 4; mi++) {
#pragma unroll
        for (int ni = 0; ni < 4; ni++) {
            const int col = bn + n_off + ni * 8 + (lane & 3) * 2;
            const float2 bs = *(const float2*)&bias[col];
#pragma unroll
            for (int h2 = 0; h2 < 2; h2++) {
                const int row = bm + m_off + mi * 16 + (lane >> 2) + h2 * 8;
                float vx = acc[mi][ni][h2 * 2 + 0] + bs.x;
                float vy = acc[mi][ni][h2 * 2 + 1] + bs.y;
                if (headsplit) {
                    const int b_ = row >> 10, s_ = row & 1023;
                    const int h_ = col >> 6,  d_ = col & 63;
                    const size_t idx = ((size_t)(b_ * NH + h_) * S + s_) * HD + d_;
                    uint32_t hp, lp;
                    split2(vx, vy, hp, lp);
                    *(uint32_t*)&dhi[idx] = hp;
                    *(uint32_t*)&dlo[idx] = lp;
                } else {
                    float2 v; v.x = vx; v.y = vy;
                    *(float2*)&g_proj[(size_t)row * H + col] = v;
                }
            }
        }
    }
}

// ---------------------------------------------------------------------------
// Flash attention (R5 version, bf16 3-term). Block = (q-tile 128, head).
// Epilogue writes tf32-rounded fp32 ctx for the Wo tf32 GEMM.
// ---------------------------------------------------------------------------
__global__ __launch_bounds__(256, 1)
void flash_attn(const float* __restrict__ mask)
{
    extern __shared__ __align__(16) char fsm[];
    uint16_t* sQhi = (uint16_t*)fsm + FQ_HI;
    uint16_t* sQlo = (uint16_t*)fsm + FQ_LO;
    uint16_t* sKhi = (uint16_t*)fsm + FK_HI;
    uint16_t* sKlo = (uint16_t*)fsm + FK_LO;
    uint16_t* sVhi = (uint16_t*)fsm + FV_HI;
    uint16_t* sVlo = (uint16_t*)fsm + FV_LO;
    float*    maskS = (float*)(fsm + FLASH_U16 * 2);

    const int head = blockIdx.y;
    const int b_   = head >> 4;
    const int h_   = head & 15;
    const size_t hbase = (size_t)head * S * HD;
    const float* mrow = mask + (size_t)b_ * S;

    const int tid  = threadIdx.x;
    const int lane = tid & 31;
    const int w    = tid >> 5;
    const int bq   = blockIdx.x * 128;

    const int lr = tid >> 1;
    const int lk = (tid & 1) * 32;

    {
        const uint4* qh4 = (const uint4*)(g_qh + hbase + (size_t)(bq + lr) * HD + lk);
        const uint4* ql4 = (const uint4*)(g_ql + hbase + (size_t)(bq + lr) * HD + lk);
        uint4* dh = (uint4*)&sQhi[lr * FROW + lk];
        uint4* dl = (uint4*)&sQlo[lr * FROW + lk];
#pragma unroll
        for (int q = 0; q < 4; q++) { dh[q] = qh4[q]; dl[q] = ql4[q]; }
    }
    __syncthreads();

    uint32_t qh[4][4], ql[4][4];
    {
        const int ar = w * 16 + (lane & 15);
        const int acb = (lane >> 4) * 8;
#pragma unroll
        for (int kk = 0; kk < 4; kk++) {
            ldm_x4(qh[kk], smem_u32(&sQhi[ar * FROW + kk * 16 + acb]));
            ldm_x4(ql[kk], smem_u32(&sQlo[ar * FROW + kk * 16 + acb]));
        }
    }

    float acco[8][4];
#pragma unroll
    for (int i = 0; i < 8; i++)
#pragma unroll
        for (int t = 0; t < 4; t++) acco[i][t] = 0.f;
    float m0 = -3.4e38f, m1 = -3.4e38f, l0 = 0.f, l1 = 0.f;

    for (int j = 0; j < S / 128; j++) {
        __syncthreads();
        {
            const size_t off = hbase + (size_t)(j * 128 + lr) * HD + lk;
            const uint4* kh4 = (const uint4*)(g_kh + off);
            const uint4* kl4 = (const uint4*)(g_kl + off);
            const uint4* vh4 = (const uint4*)(g_vh + off);
            const uint4* vl4 = (const uint4*)(g_vl + off);
            uint4* dkh = (uint4*)&sKhi[lr * FROW + lk];
            uint4* dkl = (uint4*)&sKlo[lr * FROW + lk];
            uint4* dvh = (uint4*)&sVhi[lr * FROW + lk];
            uint4* dvl = (uint4*)&sVlo[lr * FROW + lk];
#pragma unroll
            for (int q = 0; q < 4; q++) {
                dkh[q] = kh4[q]; dkl[q] = kl4[q];
                dvh[q] = vh4[q]; dvl[q] = vl4[q];
            }
            if (tid < 128) maskS[tid] = mrow[j * 128 + tid];
        }
        __syncthreads();

        float accs[16][4];
#pragma unroll
        for (int i = 0; i < 16; i++)
#pragma unroll
            for (int t = 0; t < 4; t++) accs[i][t] = 0.f;

#pragma unroll
        for (int kk = 0; kk < 4; kk++) {
            const int krow = (lane & 7) + ((lane >> 4) & 1) * 8;
            const int kcol = kk * 16 + ((lane >> 3) & 1) * 8;
#pragma unroll
            for (int np = 0; np < 8; np++) {
                uint32_t kh4[4], kl4[4];
                ldm_x4(kh4, smem_u32(&sKhi[(np * 16 + krow) * FROW + kcol]));
                ldm_x4(kl4, smem_u32(&sKlo[(np * 16 + krow) * FROW + kcol]));
                mma_bf16(accs[2*np],   qh[kk], &kh4[0]);
                mma_bf16(accs[2*np],   qh[kk], &kl4[0]);
                mma_bf16(accs[2*np],   ql[kk], &kh4[0]);
                mma_bf16(accs[2*np+1], qh[kk], &kh4[2]);
                mma_bf16(accs[2*np+1], qh[kk], &kl4[2]);
                mma_bf16(accs[2*np+1], ql[kk], &kh4[2]);
            }
        }

        float tmax0 = -3.4e38f, tmax1 = -3.4e38f;
#pragma unroll
        for (int ni = 0; ni < 16; ni++) {
            const int c = ni * 8 + (lane & 3) * 2;
            const float mk0 = maskS[c], mk1 = maskS[c + 1];
            accs[ni][0] = fmaf(accs[ni][0], SCALE, mk0);
            accs[ni][1] = fmaf(accs[ni][1], SCALE, mk1);
            accs[ni][2] = fmaf(accs[ni][2], SCALE, mk0);
            accs[ni][3] = fmaf(accs[ni][3], SCALE, mk1);
            tmax0 = fmaxf(tmax0, fmaxf(accs[ni][0], accs[ni][1]));
            tmax1 = fmaxf(tmax1, fmaxf(accs[ni][2], accs[ni][3]));
        }
        tmax0 = fmaxf(tmax0, __shfl_xor_sync(~0u, tmax0, 1));
        tmax0 = fmaxf(tmax0, __shfl_xor_sync(~0u, tmax0, 2));
        tmax1 = fmaxf(tmax1, __shfl_xor_sync(~0u, tmax1, 1));
        tmax1 = fmaxf(tmax1, __shfl_xor_sync(~0u, tmax1, 2));

        const float mn0 = fmaxf(m0, tmax0);
        const float mn1 = fmaxf(m1, tmax1);
        const float alpha0 = __expf(m0 - mn0);
        const float alpha1 = __expf(m1 - mn1);
        m0 = mn0; m1 = mn1;

        float sum0 = 0.f, sum1 = 0.f;
#pragma unroll
        for (int ni = 0; ni < 16; ni++) {
            accs[ni][0] = __expf(accs[ni][0] - mn0);
            accs[ni][1] = __expf(accs[ni][1] - mn0);
            accs[ni][2] = __expf(accs[ni][2] - mn1);
            accs[ni][3] = __expf(accs[ni][3] - mn1);
            sum0 += accs[ni][0] + accs[ni][1];
            sum1 += accs[ni][2] + accs[ni][3];
        }
        sum0 += __shfl_xor_sync(~0u, sum0, 1);
        sum0 += __shfl_xor_sync(~0u, sum0, 2);
        sum1 += __shfl_xor_sync(~0u, sum1, 1);
        sum1 += __shfl_xor_sync(~0u, sum1, 2);
        l0 = l0 * alpha0 + sum0;
        l1 = l1 * alpha1 + sum1;

#pragma unroll
        for (int ni = 0; ni < 8; ni++) {
            acco[ni][0] *= alpha0; acco[ni][1] *= alpha0;
            acco[ni][2] *= alpha1; acco[ni][3] *= alpha1;
        }

#pragma unroll
        for (int kk = 0; kk < 8; kk++) {
            uint32_t ph[4], pl[4];
            split2(accs[2*kk][0],   accs[2*kk][1],   ph[0], pl[0]);
            split2(accs[2*kk][2],   accs[2*kk][3],   ph[1], pl[1]);
            split2(accs[2*kk+1][0], accs[2*kk+1][1], ph[2], pl[2]);
            split2(accs[2*kk+1][2], accs[2*kk+1][3], ph[3], pl[3]);
            const int vrow = kk * 16 + (lane & 7) + ((lane >> 3) & 1) * 8;
#pragma unroll
            for (int np = 0; np < 4; np++) {
                const int vcol = np * 16 + (lane >> 4) * 8;
                uint32_t vh4[4], vl4[4];
                ldm_x4t(vh4, smem_u32(&sVhi[vrow * FROW + vcol]));
                ldm_x4t(vl4, smem_u32(&sVlo[vrow * FROW + vcol]));
                mma_bf16(acco[2*np],   ph, &vh4[0]);
                mma_bf16(acco[2*np],   ph, &vl4[0]);
                mma_bf16(acco[2*np],   pl, &vh4[0]);
                mma_bf16(acco[2*np+1], ph, &vh4[2]);
                mma_bf16(acco[2*np+1], ph, &vl4[2]);
                mma_bf16(acco[2*np+1], pl, &vh4[2]);
            }
        }
    }

    const float inv0 = 1.f / l0;
    const float inv1 = 1.f / l1;
    const int q0 = bq + w * 16 + (lane >> 2);
#pragma unroll
    for (int ni = 0; ni < 8; ni++) {
        const int d = ni * 8 + (lane & 3) * 2;
        const size_t i0 = ((size_t)(b_ * S + q0)) * H + h_ * HD + d;
        const size_t i1 = ((size_t)(b_ * S + q0 + 8)) * H + h_ * HD + d;
        float2 v0, v1;
        v0.x = to_tf32(acco[ni][0] * inv0); v0.y = to_tf32(acco[ni][1] * inv0);
        v1.x = to_tf32(acco[ni][2] * inv1); v1.y = to_tf32(acco[ni][3] * inv1);
        *(float2*)&g_ct[i0] = v0;
        *(float2*)&g_ct[i1] = v1;
    }
}

// ---------------------------------------------------------------------------
// out = LayerNorm(g_proj + hidden) * gamma + beta
// ---------------------------------------------------------------------------
__global__ __launch_bounds__(256, 1)
void add_ln(const float* __restrict__ hidden,
            const float* __restrict__ gamma,
            const float* __restrict__ beta,
            float* __restrict__ out)
{
    const size_t row = blockIdx.x;
    const int tid = threadIdx.x;
    __shared__ float r1[8], r2[8];

    float4 a  = *(const float4*)&g_proj[row * H + tid * 4];
    float4 hv = *(const float4*)&hidden[row * H + tid * 4];
    float x0 = a.x + hv.x, x1 = a.y + hv.y, x2 = a.z + hv.z, x3 = a.w + hv.w;

    float s1 = x0 + x1 + x2 + x3;
    float s2 = fmaf(x0, x0, fmaf(x1, x1, fmaf(x2, x2, x3 * x3)));
#pragma unroll
    for (int o = 16; o; o >>= 1) {
        s1 += __shfl_xor_sync(~0u, s1, o);
        s2 += __shfl_xor_sync(~0u, s2, o);
    }
    if ((tid & 31) == 0) { r1[tid >> 5] = s1; r2[tid >> 5] = s2; }
    __syncthreads();
    float t1 = 0.f, t2 = 0.f;
#pragma unroll
    for (int i = 0; i < 8; i++) { t1 += r1[i]; t2 += r2[i]; }

    const float mu  = t1 * (1.f / H);
    const float var = t2 * (1.f / H) - mu * mu;
    const float inv = rsqrtf(var + LN_EPS);

    float4 g  = *(const float4*)&gamma[tid * 4];
    float4 bt = *(const float4*)&beta[tid * 4];
    float4 o;
    o.x = (x0 - mu) * inv * g.x + bt.x;
    o.y = (x1 - mu) * inv * g.y + bt.y;
    o.z = (x2 - mu) * inv * g.z + bt.z;
    o.w = (x3 - mu) * inv * g.w + bt.w;
    *(float4*)&out[row * H + tid * 4] = o;
}

// ---------------------------------------------------------------------------
extern "C" void kernel_launch(void* const* d_in, const int* in_sizes, int n_in,
                              void* d_out, int out_size)
{
    const float* hidden = (const float*)d_in[0];
    const float* mask   = (const float*)d_in[1];
    const float* Wq     = (const float*)d_in[2];
    const float* bq     = (const float*)d_in[3];
    const float* Wk     = (const float*)d_in[4];
    const float* bk     = (const float*)d_in[5];
    const float* Wv     = (const float*)d_in[6];
    const float* bv     = (const float*)d_in[7];
    const float* Wo     = (const float*)d_in[8];
    const float* bo     = (const float*)d_in[9];
    const float* gamma  = (const float*)d_in[10];
    const float* beta   = (const float*)d_in[11];
    float* out          = (float*)d_out;

    cudaFuncSetAttribute(gemm_tf32, cudaFuncAttributeMaxDynamicSharedMemorySize,
                         GEMM_SMEM);
    cudaFuncSetAttribute(flash_attn, cudaFuncAttributeMaxDynamicSharedMemorySize,
                         FLASH_SMEM);

    dim3 blk(256);
    cvt_tf32<<<(M * H) / 1024, blk>>>(hidden, 0);
    cvt_tf32<<<(H * H) / 1024, blk>>>(Wq, 1);
    cvt_tf32<<<(H * H) / 1024, blk>>>(Wk, 2);
    cvt_tf32<<<(H * H) / 1024, blk>>>(Wv, 3);
    cvt_tf32<<<(H * H) / 1024, blk>>>(Wo, 4);

    dim3 gqkv(H / 128, M / 128);        // (8, 64)
    gemm_tf32<<<gqkv, blk, GEMM_SMEM>>>(bq, 0);
    gemm_tf32<<<gqkv, blk, GEMM_SMEM>>>(bk, 1);
    gemm_tf32<<<gqkv, blk, GEMM_SMEM>>>(bv, 2);

    dim3 gfa(S / 128, BH);              // (8, 128)
    flash_attn<<<gfa, blk, FLASH_SMEM>>>(mask);

    gemm_tf32<<<gqkv, blk, GEMM_SMEM>>>(bo, 3);

    add_ln<<<M, blk>>>(hidden, gamma, beta, out);
}